// round 16
// baseline (speedup 1.0000x reference)
#include <cuda_runtime.h>
#include <cstdint>

#define BB 8
#define HH 256
#define WW 256
#define NPIX (BB*HH*WW)

// ---------------- device scratch ----------------
__device__ float g_y1[BB*32*HH*WW];            // conv1 out: raw -> normalized tf32-rounded
__device__ float g_y2[(size_t)BB*64*HH*WW];    // conv2 out: raw -> normalized tf32-rounded
__device__ float g_stats[2*(32+64+128)];
__device__ float g_aff[2*(32+64+128)];
__device__ float g_gath[BB*128];

__global__ void zero_stats() {
    int i = blockIdx.x*blockDim.x + threadIdx.x;
    if (i < 448) g_stats[i] = 0.f;
}

// packed f32x2 helpers (conv1 FFMA2 path)
__device__ __forceinline__ unsigned long long pack2(float lo, float hi) {
    unsigned long long r;
    asm("mov.b64 %0, {%1, %2};" : "=l"(r) : "f"(lo), "f"(hi));
    return r;
}
__device__ __forceinline__ void unpack2(unsigned long long v, float& lo, float& hi) {
    asm("mov.b64 {%0, %1}, %2;" : "=f"(lo), "=f"(hi) : "l"(v));
}
__device__ __forceinline__ void fma2(unsigned long long& d,
                                     unsigned long long a, unsigned long long b) {
    asm("fma.rn.f32x2 %0, %1, %2, %0;" : "+l"(d) : "l"(a), "l"(b));
}
__device__ __forceinline__ uint32_t f2tf32(float x) {
    uint32_t u;
    asm("cvt.rna.tf32.f32 %0, %1;" : "=r"(u) : "f"(x));
    return u;
}

// ================= conv1: FFMA2 kernel (CIN=3) =================
template<int CIN, int COUT>
__global__ __launch_bounds__(256, 2)
void conv3x3(const float* __restrict__ in,
             const float* __restrict__ w,
             const float* __restrict__ bias,
             float* __restrict__ out,
             float* __restrict__ stats)
{
    __shared__ __align__(16) float s_w[CIN*9*16];
    __shared__ __align__(16) float s_in[2][18][66];
    __shared__ float s_red[2][16][8];

    const int tid = threadIdx.x;
    const int tx = tid & 15;
    const int ty = tid >> 4;
    const int tileX = blockIdx.x * 64, tileY = blockIdx.y * 16;
    const int ng  = COUT / 16;
    const int cog = blockIdx.z % ng;
    const int b   = blockIdx.z / ng;
    const int co0 = cog * 16;

    for (int e = tid; e < CIN*144; e += 256) {
        int ci  = e / 144;
        int rem = e - ci*144;
        int o   = rem / 9;
        int k   = rem - o*9;
        s_w[(ci*9 + k)*16 + o] = w[((co0 + o)*CIN + ci)*9 + k];
    }

    auto copy_tile = [&](int ci, int buf) {
        const float* inp = in + ((size_t)(b*CIN + ci))*HH*WW;
        #pragma unroll
        for (int it = 0; it < 5; ++it) {
            int e = tid + it*256;
            if (e < 18*66) {
                int r = e / 66, c = e - r*66;
                int gy = tileY + r - 1, gx = tileX + c - 1;
                bool ok = (unsigned)gy < (unsigned)HH && (unsigned)gx < (unsigned)WW;
                const float* src = ok ? &inp[gy*WW + gx] : inp;
                uint32_t dst = (uint32_t)__cvta_generic_to_shared(&s_in[buf][r][c]);
                int sz = ok ? 4 : 0;
                asm volatile("cp.async.ca.shared.global [%0], [%1], 4, %2;"
                             :: "r"(dst), "l"(src), "r"(sz) : "memory");
            }
        }
    };

    unsigned long long acc[8][4];
    #pragma unroll
    for (int pr = 0; pr < 8; ++pr)
        #pragma unroll
        for (int px = 0; px < 4; ++px) acc[pr][px] = 0ull;

    copy_tile(0, 0);
    asm volatile("cp.async.commit_group;" ::: "memory");
    asm volatile("cp.async.wait_group 0;" ::: "memory");
    __syncthreads();

    for (int ci = 0; ci < CIN; ++ci) {
        const int buf = ci & 1;
        const bool more = (ci + 1 < CIN);
        if (more) {
            copy_tile(ci + 1, buf ^ 1);
            asm volatile("cp.async.commit_group;" ::: "memory");
        }

        #pragma unroll
        for (int r = 0; r < 3; ++r) {
            float2 xa = *reinterpret_cast<const float2*>(&s_in[buf][ty + r][4*tx]);
            float2 xb = *reinterpret_cast<const float2*>(&s_in[buf][ty + r][4*tx + 2]);
            float2 xc = *reinterpret_cast<const float2*>(&s_in[buf][ty + r][4*tx + 4]);
            unsigned long long X[6];
            X[0] = pack2(xa.x, xa.x); X[1] = pack2(xa.y, xa.y);
            X[2] = pack2(xb.x, xb.x); X[3] = pack2(xb.y, xb.y);
            X[4] = pack2(xc.x, xc.x); X[5] = pack2(xc.y, xc.y);

            #pragma unroll
            for (int c = 0; c < 3; ++c) {
                const int k = 3*r + c;
                const float* wq = &s_w[(ci*9 + k)*16];
                unsigned long long W8[8];
                asm volatile("ld.shared.v2.b64 {%0, %1}, [%2];"
                    : "=l"(W8[0]), "=l"(W8[1])
                    : "r"((unsigned)__cvta_generic_to_shared(wq)));
                asm volatile("ld.shared.v2.b64 {%0, %1}, [%2];"
                    : "=l"(W8[2]), "=l"(W8[3])
                    : "r"((unsigned)__cvta_generic_to_shared(wq + 4)));
                asm volatile("ld.shared.v2.b64 {%0, %1}, [%2];"
                    : "=l"(W8[4]), "=l"(W8[5])
                    : "r"((unsigned)__cvta_generic_to_shared(wq + 8)));
                asm volatile("ld.shared.v2.b64 {%0, %1}, [%2];"
                    : "=l"(W8[6]), "=l"(W8[7])
                    : "r"((unsigned)__cvta_generic_to_shared(wq + 12)));

                #pragma unroll
                for (int pr = 0; pr < 8; ++pr)
                    #pragma unroll
                    for (int px = 0; px < 4; ++px)
                        fma2(acc[pr][px], W8[pr], X[c + px]);
            }
        }
        if (more) asm volatile("cp.async.wait_group 0;" ::: "memory");
        __syncthreads();
    }

    float a[16][4];
    #pragma unroll
    for (int pr = 0; pr < 8; ++pr)
        #pragma unroll
        for (int px = 0; px < 4; ++px)
            unpack2(acc[pr][px], a[2*pr][px], a[2*pr + 1][px]);
    #pragma unroll
    for (int o = 0; o < 16; ++o) {
        float bv = bias[co0 + o];
        #pragma unroll
        for (int px = 0; px < 4; ++px) a[o][px] += bv;
    }

    const int y   = tileY + ty;
    const int x0b = tileX + 4*tx;

    #pragma unroll
    for (int o = 0; o < 16; ++o) {
        *reinterpret_cast<float4*>(
            &out[(((size_t)b*COUT + co0 + o)*HH + y)*WW + x0b]) =
            make_float4(a[o][0], a[o][1], a[o][2], a[o][3]);
    }

    const int lane = tid & 31, wid = tid >> 5;
    #pragma unroll
    for (int o = 0; o < 16; ++o) {
        float s = 0.f, ss = 0.f;
        #pragma unroll
        for (int px = 0; px < 4; ++px) { s += a[o][px]; ss += a[o][px]*a[o][px]; }
        #pragma unroll
        for (int off = 16; off; off >>= 1) {
            s  += __shfl_down_sync(0xffffffffu, s,  off);
            ss += __shfl_down_sync(0xffffffffu, ss, off);
        }
        if (lane == 0) { s_red[0][o][wid] = s; s_red[1][o][wid] = ss; }
    }
    __syncthreads();
    if (tid < 16) {
        float s = 0.f, ss = 0.f;
        #pragma unroll
        for (int k = 0; k < 8; ++k) { s += s_red[0][tid][k]; ss += s_red[1][tid][k]; }
        atomicAdd(&stats[co0 + tid],        s);
        atomicAdd(&stats[COUT + co0 + tid], ss);
    }
}

// ================= conv2/conv3: implicit-GEMM tf32 mma, M=32 (2 A-frags) =========
// 256 threads = 8 warps. Tile: 64(W) x 16(H) px, 32 couts. Warp w: rows 2w,2w+1.
// CIN = 8*CHUNKS; m16n8k8 tf32. Each B fragment (b0,b1) feeds TWO mmas (frag0/frag1).
// Weight smem layout per (chunk,tap): 2 frags x [k8 x stride24 + m16] = 384 words
//   (k-stride 24 -> qk*24 mod 32 = {0,24,16,8}: conflict-free A loads).
#define CSTR 1304
#define BSTR (8*CSTR)
#define KST  24
#define TAPW 384
template<int CHUNKS, int COUT, bool WRITE_OUT, bool GATHER>
__global__ __launch_bounds__(256)
void conv_mma(const float* __restrict__ in,     // normalized tf32-rounded [B,CIN,H,W]
              const float* __restrict__ w,      // [COUT,CIN,3,3] fp32
              const float* __restrict__ bias,   // [COUT]
              float* __restrict__ out,
              float* __restrict__ stats,        // [sum COUT, sumsq COUT]
              float* __restrict__ gath,
              const int* __restrict__ nxy)
{
    constexpr int CIN = 8*CHUNKS;
    constexpr int WWORDS = CHUNKS*9*TAPW;
    extern __shared__ float sm[];
    float* s_w   = sm;
    float* s_in  = sm + WWORDS;
    float* s_red = sm + WWORDS + 2*BSTR;    // [512]: 256 sums + 256 sumsqs

    const int tid  = threadIdx.x;
    const int lane = tid & 31;
    const int warp = tid >> 5;
    const int qr   = lane >> 2;     // m row / B n index
    const int qk   = lane & 3;      // k group / D col group
    const int tileX = blockIdx.x * 64, tileY = blockIdx.y * 16;
    constexpr int NG = COUT/32;
    const int b   = blockIdx.z / NG;
    const int co0 = (blockIdx.z % NG) * 32;

    // ---- preload + tf32-convert weights: [chunk*9+tap][frag][k(stride24)][m16]
    for (int e = tid; e < CHUNKS*2304; e += 256) {
        int m   = e & 15;
        int k   = (e >> 4) & 7;
        int f   = (e >> 7) & 1;
        int ct  = e >> 8;            // chunk*9 + tap
        int chunk = ct / 9;
        int tap   = ct - chunk*9;
        int ci    = chunk*8 + k;
        float wv = w[(co0 + f*16 + m)*(CIN*9) + ci*9 + tap];
        s_w[ct*TAPW + f*192 + k*KST + m] = __uint_as_float(f2tf32(wv));
    }

    // ---- async halo copy for one 8-ci chunk: per ci 18 rows x 18 16B-granules
    auto copy_chunk = [&](int chunk, int buf) {
        const float* base = in + ((size_t)(b*CIN + chunk*8))*(HH*WW);
        #pragma unroll
        for (int it = 0; it < 11; ++it) {
            int e = tid + it*256;
            if (e < 2592) {
                int ci  = e / 324;
                int rem = e - ci*324;
                int r   = rem / 18;
                int g   = rem - r*18;
                int gy  = tileY + r - 1;
                int gxw = tileX - 4 + 4*g;
                bool ok = (gy >= 0) && (gy < HH) && (gxw >= 0) && (gxw + 3 < WW);
                const float* src = ok ? (base + ci*(HH*WW) + gy*WW + gxw) : base;
                uint32_t dst = (uint32_t)__cvta_generic_to_shared(
                    &s_in[buf*BSTR + ci*CSTR + r*72 + 4*g]);
                int sz = ok ? 16 : 0;
                asm volatile("cp.async.ca.shared.global [%0], [%1], 16, %2;"
                             :: "r"(dst), "l"(src), "r"(sz) : "memory");
            }
        }
    };

    float d0[64], d1[64];
    #pragma unroll
    for (int i = 0; i < 64; ++i) { d0[i] = 0.f; d1[i] = 0.f; }

    copy_chunk(0, 0);
    asm volatile("cp.async.commit_group;" ::: "memory");
    asm volatile("cp.async.wait_group 0;" ::: "memory");
    __syncthreads();

    for (int chunk = 0; chunk < CHUNKS; ++chunk) {
        const int buf = chunk & 1;
        const bool more = (chunk + 1 < CHUNKS);
        if (more) {
            copy_chunk(chunk + 1, buf ^ 1);
            asm volatile("cp.async.commit_group;" ::: "memory");
        }

        const float* sib = s_in + buf*BSTR;

        #pragma unroll
        for (int tap = 0; tap < 9; ++tap) {
            const int dy = tap / 3, dx = tap - 3*dy;
            const float* wq0 = s_w + (chunk*9 + tap)*TAPW + qk*KST + qr;
            const float* wq1 = wq0 + 192;
            uint32_t a00 = __float_as_uint(wq0[0]);
            uint32_t a01 = __float_as_uint(wq0[8]);
            uint32_t a02 = __float_as_uint(wq0[96]);
            uint32_t a03 = __float_as_uint(wq0[104]);
            uint32_t a10 = __float_as_uint(wq1[0]);
            uint32_t a11 = __float_as_uint(wq1[8]);
            uint32_t a12 = __float_as_uint(wq1[96]);
            uint32_t a13 = __float_as_uint(wq1[104]);

            #pragma unroll
            for (int jr = 0; jr < 2; ++jr) {
                const float* rowp = sib + (2*warp + jr + dy)*72 + 3 + dx + qr;
                #pragma unroll
                for (int jc = 0; jc < 8; ++jc) {
                    uint32_t b0 = __float_as_uint(rowp[qk*CSTR + 8*jc]);
                    uint32_t b1 = __float_as_uint(rowp[(qk + 4)*CSTR + 8*jc]);
                    float* dd0 = &d0[4*(jr*8 + jc)];
                    float* dd1 = &d1[4*(jr*8 + jc)];
                    asm("mma.sync.aligned.m16n8k8.row.col.f32.tf32.tf32.f32 "
                        "{%0,%1,%2,%3}, {%4,%5,%6,%7}, {%8,%9}, {%0,%1,%2,%3};"
                        : "+f"(dd0[0]), "+f"(dd0[1]), "+f"(dd0[2]), "+f"(dd0[3])
                        : "r"(a00), "r"(a01), "r"(a02), "r"(a03), "r"(b0), "r"(b1));
                    asm("mma.sync.aligned.m16n8k8.row.col.f32.tf32.tf32.f32 "
                        "{%0,%1,%2,%3}, {%4,%5,%6,%7}, {%8,%9}, {%0,%1,%2,%3};"
                        : "+f"(dd1[0]), "+f"(dd1[1]), "+f"(dd1[2]), "+f"(dd1[3])
                        : "r"(a10), "r"(a11), "r"(a12), "r"(a13), "r"(b0), "r"(b1));
                }
            }
        }
        if (more) asm volatile("cp.async.wait_group 0;" ::: "memory");
        __syncthreads();
    }

    // ---- bias
    {
        const float b0lo = bias[co0 + qr],      b0hi = bias[co0 + qr + 8];
        const float b1lo = bias[co0 + 16 + qr], b1hi = bias[co0 + 24 + qr];
        #pragma unroll
        for (int j = 0; j < 16; ++j) {
            d0[4*j+0] += b0lo; d0[4*j+1] += b0lo;
            d0[4*j+2] += b0hi; d0[4*j+3] += b0hi;
            d1[4*j+0] += b1lo; d1[4*j+1] += b1lo;
            d1[4*j+2] += b1hi; d1[4*j+3] += b1hi;
        }
    }

    // ---- full fragment writeback (raw conv output)
    if (WRITE_OUT) {
        #pragma unroll
        for (int jr = 0; jr < 2; ++jr) {
            const int y = tileY + 2*warp + jr;
            #pragma unroll
            for (int jc = 0; jc < 8; ++jc) {
                const int x = tileX + 8*jc + 2*qk;
                const float* dd0 = &d0[4*(jr*8 + jc)];
                const float* dd1 = &d1[4*(jr*8 + jc)];
                *reinterpret_cast<float2*>(
                    &out[((size_t)(b*COUT + co0 + qr)*HH + y)*WW + x]) =
                    make_float2(dd0[0], dd0[1]);
                *reinterpret_cast<float2*>(
                    &out[((size_t)(b*COUT + co0 + qr + 8)*HH + y)*WW + x]) =
                    make_float2(dd0[2], dd0[3]);
                *reinterpret_cast<float2*>(
                    &out[((size_t)(b*COUT + co0 + 16 + qr)*HH + y)*WW + x]) =
                    make_float2(dd1[0], dd1[1]);
                *reinterpret_cast<float2*>(
                    &out[((size_t)(b*COUT + co0 + 24 + qr)*HH + y)*WW + x]) =
                    make_float2(dd1[2], dd1[3]);
            }
        }
    }

    // ---- gather (raw conv3 at target pixel)
    if (GATHER) {
        const int ny = nxy[b*64 + 62];
        const int nx = nxy[b*64 + 63];
        if (ny >= tileY && ny < tileY + 16 && nx >= tileX && nx < tileX + 64) {
            int lr = ny - tileY, lc = nx - tileX;
            if ((lr >> 1) == warp && qk == ((lc & 7) >> 1)) {
                int jt = (lr & 1)*8 + (lc >> 3);
                int sel = lc & 1;
                #pragma unroll
                for (int j = 0; j < 16; ++j) if (j == jt) {
                    gath[b*COUT + co0 + qr]          = d0[4*j + sel];
                    gath[b*COUT + co0 + qr + 8]      = d0[4*j + 2 + sel];
                    gath[b*COUT + co0 + 16 + qr]     = d1[4*j + sel];
                    gath[b*COUT + co0 + 24 + qr]     = d1[4*j + 2 + sel];
                }
            }
        }
    }

    // ---- BN stats (both frags)
    {
        float s[4]  = {0.f, 0.f, 0.f, 0.f};   // frag0 lo/hi, frag1 lo/hi
        float ss[4] = {0.f, 0.f, 0.f, 0.f};
        #pragma unroll
        for (int j = 0; j < 16; ++j) {
            s[0]  += d0[4*j+0] + d0[4*j+1];
            ss[0] += d0[4*j+0]*d0[4*j+0] + d0[4*j+1]*d0[4*j+1];
            s[1]  += d0[4*j+2] + d0[4*j+3];
            ss[1] += d0[4*j+2]*d0[4*j+2] + d0[4*j+3]*d0[4*j+3];
            s[2]  += d1[4*j+0] + d1[4*j+1];
            ss[2] += d1[4*j+0]*d1[4*j+0] + d1[4*j+1]*d1[4*j+1];
            s[3]  += d1[4*j+2] + d1[4*j+3];
            ss[3] += d1[4*j+2]*d1[4*j+2] + d1[4*j+3]*d1[4*j+3];
        }
        #pragma unroll
        for (int q = 0; q < 4; ++q) {
            s[q]  += __shfl_down_sync(0xffffffffu, s[q],  2);
            s[q]  += __shfl_down_sync(0xffffffffu, s[q],  1);
            ss[q] += __shfl_down_sync(0xffffffffu, ss[q], 2);
            ss[q] += __shfl_down_sync(0xffffffffu, ss[q], 1);
        }
        if (qk == 0) {
            // channel rows: frag0: qr, qr+8; frag1: 16+qr, 24+qr
            s_red[(qr)*8 + warp]            = s[0];
            s_red[(qr + 8)*8 + warp]        = s[1];
            s_red[(qr + 16)*8 + warp]       = s[2];
            s_red[(qr + 24)*8 + warp]       = s[3];
            s_red[256 + (qr)*8 + warp]      = ss[0];
            s_red[256 + (qr + 8)*8 + warp]  = ss[1];
            s_red[256 + (qr + 16)*8 + warp] = ss[2];
            s_red[256 + (qr + 24)*8 + warp] = ss[3];
        }
    }
    __syncthreads();
    if (tid < 32) {
        float s = 0.f, ss = 0.f;
        #pragma unroll
        for (int k = 0; k < 8; ++k) { s += s_red[tid*8 + k]; ss += s_red[256 + tid*8 + k]; }
        atomicAdd(&stats[co0 + tid],        s);
        atomicAdd(&stats[COUT + co0 + tid], ss);
    }
}

// ---------------- BN finalize ----------------
__global__ void finalize_aff(int C, int off,
                             const float* __restrict__ gamma,
                             const float* __restrict__ beta)
{
    int c = threadIdx.x;
    if (c < C) {
        const float n = (float)NPIX;
        float m = g_stats[off + c] / n;
        float v = g_stats[off + C + c] / n - m*m;
        float a = gamma[c] * rsqrtf(v + 1e-5f);
        g_aff[off + c]     = a;
        g_aff[off + C + c] = beta[c] - m*a;
    }
}

// ---------------- normalize + tf32 round ----------------
template<int C>
__global__ __launch_bounds__(256)
void normalize_tf32(float* __restrict__ y, const float* __restrict__ aff)
{
    int i = blockIdx.x*blockDim.x + threadIdx.x;
    int c = (i >> 14) & (C - 1);
    float sA = aff[c], sB = aff[C + c];
    float4 v = reinterpret_cast<float4*>(y)[i];
    v.x = fmaf(sA, v.x, sB); v.x = (v.x > 0.f) ? v.x : 0.01f*v.x;
    v.y = fmaf(sA, v.y, sB); v.y = (v.y > 0.f) ? v.y : 0.01f*v.y;
    v.z = fmaf(sA, v.z, sB); v.z = (v.z > 0.f) ? v.z : 0.01f*v.z;
    v.w = fmaf(sA, v.w, sB); v.w = (v.w > 0.f) ? v.w : 0.01f*v.w;
    v.x = __uint_as_float(f2tf32(v.x));
    v.y = __uint_as_float(f2tf32(v.y));
    v.z = __uint_as_float(f2tf32(v.z));
    v.w = __uint_as_float(f2tf32(v.w));
    reinterpret_cast<float4*>(y)[i] = v;
}

// ---------------- tail ----------------
__global__ void tail_kernel(const float* __restrict__ image,
                            const int* __restrict__ axy,
                            const int* __restrict__ pxy,
                            const int* __restrict__ nxy,
                            float* __restrict__ out)
{
    int i = blockIdx.x*blockDim.x + threadIdx.x;
    if (i < 3528) {
        int which = i / 1176;
        int rem   = i % 1176;
        int b  = rem / 147;
        int r2 = rem % 147;
        int c  = r2 / 49;
        int p  = r2 % 49;
        int pi = p / 7, pj = p % 7;
        const int* xy = (which == 0) ? axy : (which == 1) ? pxy : nxy;
        int y0 = xy[b*64 + 62] - 3;
        int x0 = xy[b*64 + 63] - 3;
        out[i] = image[((b*3 + c)*HH + (y0 + pi))*WW + (x0 + pj)];
    } else if (i < 3528 + 1024) {
        int j = i - 3528;
        int c = j & 127;
        float v = fmaf(g_aff[192 + c], g_gath[j], g_aff[192 + 128 + c]);
        out[i] = (v > 0.f) ? v : 0.01f*v;
    }
}

// ---------------- launch ----------------
extern "C" void kernel_launch(void* const* d_in, const int* in_sizes, int n_in,
                              void* d_out, int out_size)
{
    const float* image = (const float*)d_in[0];
    const int*   axy   = (const int*)  d_in[1];
    const int*   pxy   = (const int*)  d_in[2];
    const int*   nxy   = (const int*)  d_in[3];
    const float* w1 = (const float*)d_in[4];
    const float* b1 = (const float*)d_in[5];
    const float* g1 = (const float*)d_in[6];
    const float* e1 = (const float*)d_in[7];
    const float* w2 = (const float*)d_in[8];
    const float* b2 = (const float*)d_in[9];
    const float* g2 = (const float*)d_in[10];
    const float* e2 = (const float*)d_in[11];
    const float* w3 = (const float*)d_in[12];
    const float* b3 = (const float*)d_in[13];
    const float* g3 = (const float*)d_in[14];
    const float* e3 = (const float*)d_in[15];
    float* outp = (float*)d_out;

    float *y1, *y2, *stats, *aff, *gath;
    cudaGetSymbolAddress((void**)&y1,    g_y1);
    cudaGetSymbolAddress((void**)&y2,    g_y2);
    cudaGetSymbolAddress((void**)&stats, g_stats);
    cudaGetSymbolAddress((void**)&aff,   g_aff);
    cudaGetSymbolAddress((void**)&gath,  g_gath);

    const int SMEM2 = (4*9*TAPW + 2*BSTR + 512) * 4;   // conv2: ~140.8 KB
    const int SMEM3 = (8*9*TAPW + 2*BSTR + 512) * 4;   // conv3: ~196.1 KB
    cudaFuncSetAttribute((const void*)conv_mma<4, 64, true, false>,
                         cudaFuncAttributeMaxDynamicSharedMemorySize, SMEM2);
    cudaFuncSetAttribute((const void*)conv_mma<8, 128, false, true>,
                         cudaFuncAttributeMaxDynamicSharedMemorySize, SMEM3);

    dim3 blk(256);

    zero_stats<<<2, 256>>>();

    // conv1: image -> raw y1 + stats (fp32 FFMA2)
    conv3x3<3, 32><<<dim3(4,16,BB*2), blk>>>(image, w1, b1, y1, stats + 0);
    finalize_aff<<<1, 32>>>(32, 0, g1, e1);
    normalize_tf32<32><<<(BB*32*HH*WW/4)/256, 256>>>(y1, aff + 0);

    // conv2: tf32 mma implicit GEMM, M=32 -> raw y2 + stats
    conv_mma<4, 64, true, false><<<dim3(4,16,BB*2), blk, SMEM2>>>(
        y1, w2, b2, y2, stats + 64, nullptr, nullptr);
    finalize_aff<<<1, 64>>>(64, 64, g2, e2);
    normalize_tf32<64><<<(BB*64*HH*WW/4)/256, 256>>>(y2, aff + 64);

    // conv3: tf32 mma implicit GEMM, M=32 -> stats + gathered pixels (no store)
    conv_mma<8, 128, false, true><<<dim3(4,16,BB*4), blk, SMEM3>>>(
        y2, w3, b3, nullptr, stats + 192, gath, nxy);
    finalize_aff<<<1, 128>>>(128, 192, g3, e3);

    tail_kernel<<<(3528 + 1024 + 255)/256, 256>>>(image, axy, pxy, nxy, outp);
}